// round 15
// baseline (speedup 1.0000x reference)
#include <cuda_runtime.h>
#include <cuda_bf16.h>
#include <cstdint>

// Problem constants
#define BATCH   2
#define SEQ     2048
#define EMBED   1024
#define NHEADS  16
#define HDIM    64
#define D3      (3 * EMBED)          // 3072
#define MROWS   (BATCH * SEQ)        // 4096

// ---------------------------------------------------------------------------
// Scratch (static device globals: allocation-free per harness rules)
// ---------------------------------------------------------------------------
__device__ float g_qkv [(size_t)MROWS * D3];      // (4096, 3072), tf32-rounded
__device__ float g_attn[(size_t)MROWS * EMBED];   // (4096, 1024), tf32-rounded

__device__ __align__(16) float g_x_t [(size_t)MROWS * EMBED];
__device__ __align__(16) float g_w1_t[(size_t)D3 * EMBED];
__device__ __align__(16) float g_w2_t[(size_t)EMBED * EMBED];

// ---------------------------------------------------------------------------
// PTX helpers
// ---------------------------------------------------------------------------
__device__ __forceinline__ uint32_t smem_u32(const void* p) {
    uint32_t a;
    asm("{ .reg .u64 t; cvta.to.shared.u64 t, %1; cvt.u32.u64 %0, t; }" : "=r"(a) : "l"(p));
    return a;
}
__device__ __forceinline__ void cp_async16(uint32_t dst, const void* src) {
    asm volatile("cp.async.cg.shared.global [%0], [%1], 16;" :: "r"(dst), "l"(src));
}
__device__ __forceinline__ void cp_commit() {
    asm volatile("cp.async.commit_group;" ::: "memory");
}
template <int N>
__device__ __forceinline__ void cp_wait() {
    asm volatile("cp.async.wait_group %0;" :: "n"(N) : "memory");
}
__device__ __forceinline__ uint32_t f2tf32(float f) {
    uint32_t r;
    asm("cvt.rna.tf32.f32 %0, %1;" : "=r"(r) : "f"(f));
    return r;
}
__device__ __forceinline__ float roundtf(float f) {
    return __uint_as_float(f2tf32(f));
}
__device__ __forceinline__ void mma_tf32(float* c, const uint32_t* a, const uint32_t* b) {
    asm volatile(
        "mma.sync.aligned.m16n8k8.row.col.f32.tf32.tf32.f32 "
        "{%0,%1,%2,%3}, {%4,%5,%6,%7}, {%8,%9}, {%0,%1,%2,%3};"
        : "+f"(c[0]), "+f"(c[1]), "+f"(c[2]), "+f"(c[3])
        : "r"(a[0]), "r"(a[1]), "r"(a[2]), "r"(a[3]), "r"(b[0]), "r"(b[1]));
}

// ---------------------------------------------------------------------------
// fp32 -> tf32-rounded fp32 copy (float4)
// ---------------------------------------------------------------------------
__global__ void round_tf32_kernel(const float* __restrict__ src,
                                  float* __restrict__ dst, int n4)
{
    int i = blockIdx.x * blockDim.x + threadIdx.x;
    if (i >= n4) return;
    float4 v = reinterpret_cast<const float4*>(src)[i];
    float4 o;
    o.x = roundtf(v.x); o.y = roundtf(v.y); o.z = roundtf(v.z); o.w = roundtf(v.w);
    reinterpret_cast<float4*>(dst)[i] = o;
}

// ---------------------------------------------------------------------------
// TF32 GEMM: C[M,N] = A[M,K] * B[N,K]^T, pre-rounded inputs.
// BM=BN=128, BK=32, 4 warps, warp tile 64x64, 2 CTAs/SM, 2-stage cp.async.
// K-PERMUTED fragments (slot tc <-> logical 2tc, slot tc+4 <-> 2tc+1) with
// stride 40 floats: S ≡ 8 (mod 32) -> LDS.64 conflict-free in both phases.
//   A frag = 2x LDS.64, B frag = 1x LDS.64.
// ---------------------------------------------------------------------------
#define GROWF    40
#define GROWB    (GROWF * 4)                 // 160 bytes
#define GTILE_B  (128 * GROWB)               // 20480
#define GSTAGE_B (2 * GTILE_B)               // 40960
#define GEMM_SMEM (2 * GSTAGE_B)             // 81920

__device__ __forceinline__ void load_stage_tf32(uint32_t sbase,
                                                const float* __restrict__ A,
                                                const float* __restrict__ B,
                                                int bm, int bn, int K, int k0, int tid)
{
#pragma unroll
    for (int rep = 0; rep < 16; rep++) {
        const int t = rep >> 3;
        int e   = tid + (rep & 7) * 128;
        int row = e >> 3;
        int ch  = e & 7;
        const float* src = (t == 0)
            ? A + (size_t)(bm + row) * K + k0 + ch * 4
            : B + (size_t)(bn + row) * K + k0 + ch * 4;
        cp_async16(sbase + (uint32_t)t * GTILE_B + (uint32_t)(row * GROWB + ch * 16), src);
    }
}

template <bool ROUND_C>
__global__ __launch_bounds__(128, 2) void gemm_tf32(
    const float* __restrict__ A, const float* __restrict__ B,
    float* __restrict__ C, int M, int N, int K)
{
    extern __shared__ __align__(16) float dynf[];
    const uint32_t sb = smem_u32(dynf);

    const int tid  = threadIdx.x;
    const int lane = tid & 31;
    const int wid  = tid >> 5;
    const int wm   = wid >> 1;
    const int wn   = wid & 1;
    const int tr   = lane >> 2;
    const int tc   = lane & 3;
    const int bm   = blockIdx.y * 128;
    const int bn   = blockIdx.x * 128;

    float acc[4][8][4];
#pragma unroll
    for (int i = 0; i < 4; i++)
#pragma unroll
        for (int j = 0; j < 8; j++)
#pragma unroll
            for (int k = 0; k < 4; k++) acc[i][j][k] = 0.f;

    const int NIT = K / 32;

    load_stage_tf32(sb, A, B, bm, bn, K, 0, tid);
    cp_commit();

    for (int it = 0; it < NIT; it++) {
        if (it + 1 < NIT) {
            load_stage_tf32(sb + (uint32_t)((it + 1) & 1) * GSTAGE_B,
                            A, B, bm, bn, K, (it + 1) * 32, tid);
            cp_commit();
            cp_wait<1>();
        } else {
            cp_wait<0>();
        }
        __syncthreads();

        const float* As = dynf + (size_t)(it & 1) * (GSTAGE_B / 4);
        const float* Bs = As + GTILE_B / 4;
        // k-permuted fragment bases: logical k pair (2tc, 2tc+1) contiguous
        const float* apbase = As + (size_t)(wm * 64 + tr) * GROWF + 2 * tc;
        const float* bpbase = Bs + (size_t)(wn * 64 + tr) * GROWF + 2 * tc;

#pragma unroll
        for (int kt = 0; kt < 4; kt++) {
            const int k0 = kt * 8;

            uint32_t afr[4][4];
#pragma unroll
            for (int mt = 0; mt < 4; mt++) {
                const float* ap = apbase + (size_t)mt * 16 * GROWF + k0;
                float2 lo = *reinterpret_cast<const float2*>(ap);
                float2 hi = *reinterpret_cast<const float2*>(ap + 8 * GROWF);
                afr[mt][0] = __float_as_uint(lo.x);
                afr[mt][2] = __float_as_uint(lo.y);
                afr[mt][1] = __float_as_uint(hi.x);
                afr[mt][3] = __float_as_uint(hi.y);
            }

#pragma unroll
            for (int nt = 0; nt < 8; nt++) {
                float2 bv = *reinterpret_cast<const float2*>(
                    bpbase + (size_t)nt * 8 * GROWF + k0);
                uint32_t bb[2];
                bb[0] = __float_as_uint(bv.x);
                bb[1] = __float_as_uint(bv.y);
#pragma unroll
                for (int mt = 0; mt < 4; mt++)
                    mma_tf32(acc[mt][nt], afr[mt], bb);
            }
        }
        __syncthreads();
    }

#pragma unroll
    for (int mt = 0; mt < 4; mt++) {
        int row = bm + wm * 64 + mt * 16 + tr;
#pragma unroll
        for (int nt = 0; nt < 8; nt++) {
            int col = bn + wn * 64 + nt * 8 + tc * 2;
            float c0 = acc[mt][nt][0], c1 = acc[mt][nt][1];
            float c2 = acc[mt][nt][2], c3 = acc[mt][nt][3];
            if (ROUND_C) {
                c0 = roundtf(c0); c1 = roundtf(c1);
                c2 = roundtf(c2); c3 = roundtf(c3);
            }
            *reinterpret_cast<float2*>(&C[(size_t)row * N + col]) = make_float2(c0, c1);
            *reinterpret_cast<float2*>(&C[(size_t)(row + 8) * N + col]) = make_float2(c2, c3);
        }
    }
}

// ---------------------------------------------------------------------------
// TF32 causal flash attention (R13/R14 proven config, unchanged):
//  - S-loop: k-permuted Q/K fragments via LDS.64 (K stride 72 ≡ 8 mod 32)
//  - PV-loop: P A-fragment IS the S C-fragment (zero shuffles), V stride 68
//  - 3-stage cp.async K/V, one sync per key tile
// ---------------------------------------------------------------------------
#define TQA   128
#define TKA   64
#define PK_K  72
#define PK_V  68
#define KT_F  (64 * PK_K)
#define VT_F  (64 * PK_V)
#define STG_F (KT_F + VT_F)
#define ATT_SMEM (3 * STG_F * 4)            // 107520 bytes

__device__ __forceinline__ void attn_load_kv(uint32_t sst,
                                             const float* __restrict__ kptr,
                                             const float* __restrict__ vptr,
                                             int kb, int tid)
{
#pragma unroll
    for (int rep = 0; rep < 4; rep++) {
        int i = tid + rep * 256;
        int r = i >> 4, c4 = (i & 15) * 4;
        cp_async16(sst + (uint32_t)(r * PK_K + c4) * 4,
                   kptr + (size_t)(kb + r) * D3 + c4);
        cp_async16(sst + KT_F * 4 + (uint32_t)(r * PK_V + c4) * 4,
                   vptr + (size_t)(kb + r) * D3 + c4);
    }
    cp_commit();
}

__global__ __launch_bounds__(256, 1) void attn_tc_kernel()
{
    extern __shared__ float smf[];

    const int tid  = threadIdx.x;
    const int lane = tid & 31;
    const int w    = tid >> 5;
    const int tr   = lane >> 2;
    const int tc   = lane & 3;

    const int qi = (int)gridDim.x - 1 - (int)blockIdx.x;
    const int h  = blockIdx.y;
    const int b  = blockIdx.z;
    const int qb = qi * TQA;
    const size_t rowbase = (size_t)b * SEQ;

    const float* qptr = g_qkv + rowbase * D3 + h * HDIM;
    const float* kptr = qptr + EMBED;
    const float* vptr = qptr + 2 * EMBED;

    // Stage Q tile through smem (stride PK_K), then to registers (k-permuted).
    for (int i = tid; i < 128 * 16; i += 256) {
        int r = i >> 4, c4 = (i & 15) * 4;
        float4 v = *reinterpret_cast<const float4*>(qptr + (size_t)(qb + r) * D3 + c4);
        float* dst = smf + r * PK_K + c4;
        dst[0] = v.x; dst[1] = v.y; dst[2] = v.z; dst[3] = v.w;
    }
    __syncthreads();

    uint32_t qfrag[8][4];
    {
        const float* qrow = smf + (size_t)(w * 16 + tr) * PK_K + 2 * tc;
#pragma unroll
        for (int kt = 0; kt < 8; kt++) {
            float2 lo = *reinterpret_cast<const float2*>(qrow + kt * 8);
            float2 hi = *reinterpret_cast<const float2*>(qrow + 8 * PK_K + kt * 8);
            qfrag[kt][0] = __float_as_uint(lo.x);
            qfrag[kt][2] = __float_as_uint(lo.y);
            qfrag[kt][1] = __float_as_uint(hi.x);
            qfrag[kt][3] = __float_as_uint(hi.y);
        }
    }
    __syncthreads();

    const uint32_t s0 = smem_u32(smf);

    float oacc[8][4];
#pragma unroll
    for (int nt = 0; nt < 8; nt++)
#pragma unroll
        for (int e = 0; e < 4; e++) oacc[nt][e] = 0.f;

    float m0 = -1e30f, m1 = -1e30f, l0 = 0.f, l1 = 0.f;

    const float CSC = 0.18033688f;
    const int wrow  = qb + w * 16;
    const int gr0   = wrow + tr;
    const int jmax  = (qb + TQA - 1) / TKA;

    attn_load_kv(s0 + 0u * STG_F * 4, kptr, vptr, 0, tid);
    attn_load_kv(s0 + 1u * STG_F * 4, kptr, vptr, TKA, tid);

    int st_cur = 0, st_nxt = 2;

    for (int j = 0; j <= jmax; j++) {
        const int kb = j * TKA;

        if (j < jmax) cp_wait<1>(); else cp_wait<0>();
        __syncthreads();

        if (j + 2 <= jmax)
            attn_load_kv(s0 + (uint32_t)st_nxt * STG_F * 4, kptr, vptr, (j + 2) * TKA, tid);

        const float* Ksm = smf + st_cur * STG_F;
        const float* Vsm = Ksm + KT_F;

        if (kb <= wrow + 15) {
            float sacc[8][4];
#pragma unroll
            for (int nt = 0; nt < 8; nt++)
#pragma unroll
                for (int e = 0; e < 4; e++) sacc[nt][e] = 0.f;

            const float* kbase = Ksm + (size_t)tr * PK_K + 2 * tc;
#pragma unroll
            for (int kt = 0; kt < 8; kt++) {
#pragma unroll
                for (int nt = 0; nt < 8; nt++) {
                    float2 kv2 = *reinterpret_cast<const float2*>(
                        kbase + (size_t)nt * 8 * PK_K + kt * 8);
                    uint32_t bb[2];
                    bb[0] = __float_as_uint(kv2.x);
                    bb[1] = __float_as_uint(kv2.y);
                    mma_tf32(sacc[nt], qfrag[kt], bb);
                }
            }

            const bool need_mask = (kb + TKA - 1) > wrow;
            float mx0 = -1e30f, mx1 = -1e30f;
#pragma unroll
            for (int nt = 0; nt < 8; nt++) {
                int c0 = kb + nt * 8 + 2 * tc;
                float z0 = sacc[nt][0] * CSC;
                float z1 = sacc[nt][1] * CSC;
                float z2 = sacc[nt][2] * CSC;
                float z3 = sacc[nt][3] * CSC;
                if (need_mask) {
                    if (c0     > gr0) z0 = -1e30f;
                    if (c0 + 1 > gr0) z1 = -1e30f;
                    if (c0     > gr0 + 8) z2 = -1e30f;
                    if (c0 + 1 > gr0 + 8) z3 = -1e30f;
                }
                sacc[nt][0] = z0; sacc[nt][1] = z1;
                sacc[nt][2] = z2; sacc[nt][3] = z3;
                mx0 = fmaxf(mx0, fmaxf(z0, z1));
                mx1 = fmaxf(mx1, fmaxf(z2, z3));
            }
            mx0 = fmaxf(mx0, __shfl_xor_sync(0xffffffffu, mx0, 1));
            mx0 = fmaxf(mx0, __shfl_xor_sync(0xffffffffu, mx0, 2));
            mx1 = fmaxf(mx1, __shfl_xor_sync(0xffffffffu, mx1, 1));
            mx1 = fmaxf(mx1, __shfl_xor_sync(0xffffffffu, mx1, 2));

            float m0n = fmaxf(m0, mx0);
            float m1n = fmaxf(m1, mx1);
            float f0 = exp2f(m0 - m0n);
            float f1 = exp2f(m1 - m1n);

            uint32_t pcu[8][4];
            float sum0 = 0.f, sum1 = 0.f;
#pragma unroll
            for (int nt = 0; nt < 8; nt++) {
                float p00 = exp2f(sacc[nt][0] - m0n);
                float p01 = exp2f(sacc[nt][1] - m0n);
                float p10 = exp2f(sacc[nt][2] - m1n);
                float p11 = exp2f(sacc[nt][3] - m1n);
                sum0 += p00 + p01;
                sum1 += p10 + p11;
                pcu[nt][0] = f2tf32(p00);
                pcu[nt][1] = f2tf32(p01);
                pcu[nt][2] = f2tf32(p10);
                pcu[nt][3] = f2tf32(p11);
            }
            sum0 += __shfl_xor_sync(0xffffffffu, sum0, 1);
            sum0 += __shfl_xor_sync(0xffffffffu, sum0, 2);
            sum1 += __shfl_xor_sync(0xffffffffu, sum1, 1);
            sum1 += __shfl_xor_sync(0xffffffffu, sum1, 2);

            l0 = l0 * f0 + sum0;
            l1 = l1 * f1 + sum1;
            m0 = m0n; m1 = m1n;
#pragma unroll
            for (int nt = 0; nt < 8; nt++) {
                oacc[nt][0] *= f0; oacc[nt][1] *= f0;
                oacc[nt][2] *= f1; oacc[nt][3] *= f1;
            }

            // ---- O += P @ V : C-fragment IS the k-permuted A-fragment ----
#pragma unroll
            for (int kt = 0; kt < 8; kt++) {
                uint32_t pa[4];
                pa[0] = pcu[kt][0];
                pa[1] = pcu[kt][2];
                pa[2] = pcu[kt][1];
                pa[3] = pcu[kt][3];
                const float* vrow = Vsm + (size_t)(kt * 8 + 2 * tc) * PK_V;
#pragma unroll
                for (int nt = 0; nt < 8; nt++) {
                    uint32_t vb[2];
                    vb[0] = __float_as_uint(vrow[nt * 8 + tr]);
                    vb[1] = __float_as_uint(vrow[PK_V + nt * 8 + tr]);
                    mma_tf32(oacc[nt], pa, vb);
                }
            }
        }

        st_cur = (st_cur == 2) ? 0 : st_cur + 1;
        st_nxt = (st_nxt == 2) ? 0 : st_nxt + 1;
    }

    // Epilogue: normalize, round to tf32, write to g_attn
    float il0 = 1.0f / l0;
    float il1 = 1.0f / l1;
    float* obase = g_attn + (size_t)(rowbase + gr0) * EMBED + h * HDIM + 2 * tc;
#pragma unroll
    for (int nt = 0; nt < 8; nt++) {
        *reinterpret_cast<float2*>(obase + nt * 8) =
            make_float2(roundtf(oacc[nt][0] * il0), roundtf(oacc[nt][1] * il0));
        *reinterpret_cast<float2*>(obase + 8 * EMBED + nt * 8) =
            make_float2(roundtf(oacc[nt][2] * il1), roundtf(oacc[nt][3] * il1));
    }
}

// ---------------------------------------------------------------------------
// Launch
// ---------------------------------------------------------------------------
extern "C" void kernel_launch(void* const* d_in, const int* in_sizes, int n_in,
                              void* d_out, int out_size)
{
    const float* x     = (const float*)d_in[0];
    const float* qkv_w = (const float*)d_in[1];
    const float* out_w = (const float*)d_in[2];
    float* out = (float*)d_out;

    static bool attr_done = false;
    if (!attr_done) {
        cudaFuncSetAttribute(gemm_tf32<true>,  cudaFuncAttributeMaxDynamicSharedMemorySize, GEMM_SMEM);
        cudaFuncSetAttribute(gemm_tf32<false>, cudaFuncAttributeMaxDynamicSharedMemorySize, GEMM_SMEM);
        cudaFuncSetAttribute(attn_tc_kernel,   cudaFuncAttributeMaxDynamicSharedMemorySize, ATT_SMEM);
        attr_done = true;
    }

    float *qkv, *attn, *xt, *w1t, *w2t;
    cudaGetSymbolAddress((void**)&qkv,  g_qkv);
    cudaGetSymbolAddress((void**)&attn, g_attn);
    cudaGetSymbolAddress((void**)&xt,   g_x_t);
    cudaGetSymbolAddress((void**)&w1t,  g_w1_t);
    cudaGetSymbolAddress((void**)&w2t,  g_w2_t);

    // 0) pre-round inputs to tf32
    {
        int n1 = MROWS * EMBED / 4;
        round_tf32_kernel<<<(n1 + 255) / 256, 256>>>(x, xt, n1);
        int n2 = D3 * EMBED / 4;
        round_tf32_kernel<<<(n2 + 255) / 256, 256>>>(qkv_w, w1t, n2);
        int n3 = EMBED * EMBED / 4;
        round_tf32_kernel<<<(n3 + 255) / 256, 256>>>(out_w, w2t, n3);
    }

    // 1) QKV projection
    {
        dim3 grid(D3 / 128, MROWS / 128);
        gemm_tf32<true><<<grid, 128, GEMM_SMEM>>>(xt, w1t, qkv, MROWS, D3, EMBED);
    }

    // 2) Causal flash attention
    {
        dim3 grid(SEQ / TQA, NHEADS, BATCH);
        attn_tc_kernel<<<grid, 256, ATT_SMEM>>>();
    }

    // 3) Output projection
    {
        dim3 grid(EMBED / 128, MROWS / 128);
        gemm_tf32<false><<<grid, 128, GEMM_SMEM>>>(attn, w2t, out, MROWS, EMBED, EMBED);
    }
}

// round 16
// speedup vs baseline: 1.0542x; 1.0542x over previous
#include <cuda_runtime.h>
#include <cuda_bf16.h>
#include <cstdint>

// Problem constants
#define BATCH   2
#define SEQ     2048
#define EMBED   1024
#define NHEADS  16
#define HDIM    64
#define D3      (3 * EMBED)          // 3072
#define MROWS   (BATCH * SEQ)        // 4096

// ---------------------------------------------------------------------------
// Scratch (static device globals: allocation-free per harness rules)
// ---------------------------------------------------------------------------
__device__ float g_qkv [(size_t)MROWS * D3];      // (4096, 3072), tf32-rounded
__device__ float g_attn[(size_t)MROWS * EMBED];   // (4096, 1024), tf32-rounded

__device__ __align__(16) float g_x_t [(size_t)MROWS * EMBED];
__device__ __align__(16) float g_w1_t[(size_t)D3 * EMBED];
__device__ __align__(16) float g_w2_t[(size_t)EMBED * EMBED];

// ---------------------------------------------------------------------------
// PTX helpers
// ---------------------------------------------------------------------------
__device__ __forceinline__ uint32_t smem_u32(const void* p) {
    uint32_t a;
    asm("{ .reg .u64 t; cvta.to.shared.u64 t, %1; cvt.u32.u64 %0, t; }" : "=r"(a) : "l"(p));
    return a;
}
__device__ __forceinline__ void cp_async16(uint32_t dst, const void* src) {
    asm volatile("cp.async.cg.shared.global [%0], [%1], 16;" :: "r"(dst), "l"(src));
}
__device__ __forceinline__ void cp_commit() {
    asm volatile("cp.async.commit_group;" ::: "memory");
}
template <int N>
__device__ __forceinline__ void cp_wait() {
    asm volatile("cp.async.wait_group %0;" :: "n"(N) : "memory");
}
__device__ __forceinline__ uint32_t f2tf32(float f) {
    uint32_t r;
    asm("cvt.rna.tf32.f32 %0, %1;" : "=r"(r) : "f"(f));
    return r;
}
__device__ __forceinline__ float roundtf(float f) {
    return __uint_as_float(f2tf32(f));
}
__device__ __forceinline__ void mma_tf32(float* c, const uint32_t* a, const uint32_t* b) {
    asm volatile(
        "mma.sync.aligned.m16n8k8.row.col.f32.tf32.tf32.f32 "
        "{%0,%1,%2,%3}, {%4,%5,%6,%7}, {%8,%9}, {%0,%1,%2,%3};"
        : "+f"(c[0]), "+f"(c[1]), "+f"(c[2]), "+f"(c[3])
        : "r"(a[0]), "r"(a[1]), "r"(a[2]), "r"(a[3]), "r"(b[0]), "r"(b[1]));
}

// ---------------------------------------------------------------------------
// Fused fp32 -> tf32-rounded copy over three concatenated tensors.
// Segment boundaries in float4 units.
// ---------------------------------------------------------------------------
#define N4_X   (MROWS * EMBED / 4)            // 1048576
#define N4_W1  (D3 * EMBED / 4)               // 786432
#define N4_W2  (EMBED * EMBED / 4)            // 262144
#define N4_ALL (N4_X + N4_W1 + N4_W2)

__global__ void round_all_kernel(const float* __restrict__ x,
                                 const float* __restrict__ w1,
                                 const float* __restrict__ w2,
                                 float* __restrict__ xt,
                                 float* __restrict__ w1t,
                                 float* __restrict__ w2t)
{
    int i = blockIdx.x * blockDim.x + threadIdx.x;
    if (i >= N4_ALL) return;
    const float4* src;
    float4* dst;
    if (i < N4_X) {
        src = reinterpret_cast<const float4*>(x) + i;
        dst = reinterpret_cast<float4*>(xt) + i;
    } else if (i < N4_X + N4_W1) {
        src = reinterpret_cast<const float4*>(w1) + (i - N4_X);
        dst = reinterpret_cast<float4*>(w1t) + (i - N4_X);
    } else {
        src = reinterpret_cast<const float4*>(w2) + (i - N4_X - N4_W1);
        dst = reinterpret_cast<float4*>(w2t) + (i - N4_X - N4_W1);
    }
    float4 v = *src;
    float4 o;
    o.x = roundtf(v.x); o.y = roundtf(v.y); o.z = roundtf(v.z); o.w = roundtf(v.w);
    *dst = o;
}

// ---------------------------------------------------------------------------
// TF32 GEMM (R14 proven config): C[M,N] = A[M,K] * B[N,K]^T.
// BM=BN=128, BK=32, 4 warps, warp tile 64x64, 2 CTAs/SM, 3-stage cp.async.
// Scalar-LDS fragments from stride-36 rows (conflict-free), no CVT in loop.
// ---------------------------------------------------------------------------
#define GROWF    36
#define GROWB    (GROWF * 4)
#define GTILE_B  (128 * GROWB)               // 18432
#define GSTAGE_B (2 * GTILE_B)               // 36864
#define GEMM_SMEM (3 * GSTAGE_B)             // 110592

__device__ __forceinline__ void load_stage_tf32(uint32_t sbase,
                                                const float* __restrict__ A,
                                                const float* __restrict__ B,
                                                int bm, int bn, int K, int k0, int tid)
{
#pragma unroll
    for (int rep = 0; rep < 16; rep++) {
        const int t = rep >> 3;
        int e   = tid + (rep & 7) * 128;
        int row = e >> 3;
        int ch  = e & 7;
        const float* src = (t == 0)
            ? A + (size_t)(bm + row) * K + k0 + ch * 4
            : B + (size_t)(bn + row) * K + k0 + ch * 4;
        cp_async16(sbase + (uint32_t)t * GTILE_B + (uint32_t)(row * GROWB + ch * 16), src);
    }
}

template <bool ROUND_C>
__global__ __launch_bounds__(128, 2) void gemm_tf32(
    const float* __restrict__ A, const float* __restrict__ B,
    float* __restrict__ C, int M, int N, int K)
{
    extern __shared__ __align__(16) float dynf[];
    const uint32_t sb = smem_u32(dynf);

    const int tid  = threadIdx.x;
    const int lane = tid & 31;
    const int wid  = tid >> 5;
    const int wm   = wid >> 1;
    const int wn   = wid & 1;
    const int tr   = lane >> 2;
    const int tc   = lane & 3;
    const int bm   = blockIdx.y * 128;
    const int bn   = blockIdx.x * 128;

    float acc[4][8][4];
#pragma unroll
    for (int i = 0; i < 4; i++)
#pragma unroll
        for (int j = 0; j < 8; j++)
#pragma unroll
            for (int k = 0; k < 4; k++) acc[i][j][k] = 0.f;

    const int NIT = K / 32;

    load_stage_tf32(sb + 0u * GSTAGE_B, A, B, bm, bn, K, 0, tid);
    cp_commit();
    load_stage_tf32(sb + 1u * GSTAGE_B, A, B, bm, bn, K, 32, tid);
    cp_commit();

    int st_cur = 0, st_nxt = 2;

    for (int it = 0; it < NIT; it++) {
        if (it + 1 < NIT) cp_wait<1>(); else cp_wait<0>();
        __syncthreads();

        if (it + 2 < NIT) {
            load_stage_tf32(sb + (uint32_t)st_nxt * GSTAGE_B,
                            A, B, bm, bn, K, (it + 2) * 32, tid);
            cp_commit();
        }

        const float* As = dynf + (size_t)st_cur * (GSTAGE_B / 4);
        const float* Bs = As + GTILE_B / 4;

#pragma unroll
        for (int kt = 0; kt < 4; kt++) {
            const int k0 = kt * 8;

            uint32_t afr[4][4];
#pragma unroll
            for (int mt = 0; mt < 4; mt++) {
                const float* ap = As + (size_t)(wm * 64 + mt * 16 + tr) * GROWF + k0 + tc;
                afr[mt][0] = __float_as_uint(ap[0]);
                afr[mt][1] = __float_as_uint(ap[8 * GROWF]);
                afr[mt][2] = __float_as_uint(ap[4]);
                afr[mt][3] = __float_as_uint(ap[8 * GROWF + 4]);
            }

#pragma unroll
            for (int nt = 0; nt < 8; nt++) {
                const float* bp = Bs + (size_t)(wn * 64 + nt * 8 + tr) * GROWF + k0 + tc;
                uint32_t bb[2];
                bb[0] = __float_as_uint(bp[0]);
                bb[1] = __float_as_uint(bp[4]);
#pragma unroll
                for (int mt = 0; mt < 4; mt++)
                    mma_tf32(acc[mt][nt], afr[mt], bb);
            }
        }

        st_cur = (st_cur == 2) ? 0 : st_cur + 1;
        st_nxt = (st_nxt == 2) ? 0 : st_nxt + 1;
    }

#pragma unroll
    for (int mt = 0; mt < 4; mt++) {
        int row = bm + wm * 64 + mt * 16 + tr;
#pragma unroll
        for (int nt = 0; nt < 8; nt++) {
            int col = bn + wn * 64 + nt * 8 + tc * 2;
            float c0 = acc[mt][nt][0], c1 = acc[mt][nt][1];
            float c2 = acc[mt][nt][2], c3 = acc[mt][nt][3];
            if (ROUND_C) {
                c0 = roundtf(c0); c1 = roundtf(c1);
                c2 = roundtf(c2); c3 = roundtf(c3);
            }
            *reinterpret_cast<float2*>(&C[(size_t)row * N + col]) = make_float2(c0, c1);
            *reinterpret_cast<float2*>(&C[(size_t)(row + 8) * N + col]) = make_float2(c2, c3);
        }
    }
}

// ---------------------------------------------------------------------------
// TF32 causal flash attention (R13/R14 proven config, unchanged):
//  - S-loop: k-permuted Q/K fragments via LDS.64 (K stride 72 ≡ 8 mod 32)
//  - PV-loop: P A-fragment IS the S C-fragment (zero shuffles), V stride 68
//  - 3-stage cp.async K/V, one sync per key tile
// ---------------------------------------------------------------------------
#define TQA   128
#define TKA   64
#define PK_K  72
#define PK_V  68
#define KT_F  (64 * PK_K)
#define VT_F  (64 * PK_V)
#define STG_F (KT_F + VT_F)
#define ATT_SMEM (3 * STG_F * 4)            // 107520 bytes

__device__ __forceinline__ void attn_load_kv(uint32_t sst,
                                             const float* __restrict__ kptr,
                                             const float* __restrict__ vptr,
                                             int kb, int tid)
{
#pragma unroll
    for (int rep = 0; rep < 4; rep++) {
        int i = tid + rep * 256;
        int r = i >> 4, c4 = (i & 15) * 4;
        cp_async16(sst + (uint32_t)(r * PK_K + c4) * 4,
                   kptr + (size_t)(kb + r) * D3 + c4);
        cp_async16(sst + KT_F * 4 + (uint32_t)(r * PK_V + c4) * 4,
                   vptr + (size_t)(kb + r) * D3 + c4);
    }
    cp_commit();
}

__global__ __launch_bounds__(256, 1) void attn_tc_kernel()
{
    extern __shared__ float smf[];

    const int tid  = threadIdx.x;
    const int lane = tid & 31;
    const int w    = tid >> 5;
    const int tr   = lane >> 2;
    const int tc   = lane & 3;

    const int qi = (int)gridDim.x - 1 - (int)blockIdx.x;
    const int h  = blockIdx.y;
    const int b  = blockIdx.z;
    const int qb = qi * TQA;
    const size_t rowbase = (size_t)b * SEQ;

    const float* qptr = g_qkv + rowbase * D3 + h * HDIM;
    const float* kptr = qptr + EMBED;
    const float* vptr = qptr + 2 * EMBED;

    // Stage Q tile through smem (stride PK_K), then to registers (k-permuted).
    for (int i = tid; i < 128 * 16; i += 256) {
        int r = i >> 4, c4 = (i & 15) * 4;
        float4 v = *reinterpret_cast<const float4*>(qptr + (size_t)(qb + r) * D3 + c4);
        float* dst = smf + r * PK_K + c4;
        dst[0] = v.x; dst[1] = v.y; dst[2] = v.z; dst[3] = v.w;
    }
    __syncthreads();

    uint32_t qfrag[8][4];
    {
        const float* qrow = smf + (size_t)(w * 16 + tr) * PK_K + 2 * tc;
#pragma unroll
        for (int kt = 0; kt < 8; kt++) {
            float2 lo = *reinterpret_cast<const float2*>(qrow + kt * 8);
            float2 hi = *reinterpret_cast<const float2*>(qrow + 8 * PK_K + kt * 8);
            qfrag[kt][0] = __float_as_uint(lo.x);
            qfrag[kt][2] = __float_as_uint(lo.y);
            qfrag[kt][1] = __float_as_uint(hi.x);
            qfrag[kt][3] = __float_as_uint(hi.y);
        }
    }
    __syncthreads();

    const uint32_t s0 = smem_u32(smf);

    float oacc[8][4];
#pragma unroll
    for (int nt = 0; nt < 8; nt++)
#pragma unroll
        for (int e = 0; e < 4; e++) oacc[nt][e] = 0.f;

    float m0 = -1e30f, m1 = -1e30f, l0 = 0.f, l1 = 0.f;

    const float CSC = 0.18033688f;
    const int wrow  = qb + w * 16;
    const int gr0   = wrow + tr;
    const int jmax  = (qb + TQA - 1) / TKA;

    attn_load_kv(s0 + 0u * STG_F * 4, kptr, vptr, 0, tid);
    attn_load_kv(s0 + 1u * STG_F * 4, kptr, vptr, TKA, tid);

    int st_cur = 0, st_nxt = 2;

    for (int j = 0; j <= jmax; j++) {
        const int kb = j * TKA;

        if (j < jmax) cp_wait<1>(); else cp_wait<0>();
        __syncthreads();

        if (j + 2 <= jmax)
            attn_load_kv(s0 + (uint32_t)st_nxt * STG_F * 4, kptr, vptr, (j + 2) * TKA, tid);

        const float* Ksm = smf + st_cur * STG_F;
        const float* Vsm = Ksm + KT_F;

        if (kb <= wrow + 15) {
            float sacc[8][4];
#pragma unroll
            for (int nt = 0; nt < 8; nt++)
#pragma unroll
                for (int e = 0; e < 4; e++) sacc[nt][e] = 0.f;

            const float* kbase = Ksm + (size_t)tr * PK_K + 2 * tc;
#pragma unroll
            for (int kt = 0; kt < 8; kt++) {
#pragma unroll
                for (int nt = 0; nt < 8; nt++) {
                    float2 kv2 = *reinterpret_cast<const float2*>(
                        kbase + (size_t)nt * 8 * PK_K + kt * 8);
                    uint32_t bb[2];
                    bb[0] = __float_as_uint(kv2.x);
                    bb[1] = __float_as_uint(kv2.y);
                    mma_tf32(sacc[nt], qfrag[kt], bb);
                }
            }

            const bool need_mask = (kb + TKA - 1) > wrow;
            float mx0 = -1e30f, mx1 = -1e30f;
#pragma unroll
            for (int nt = 0; nt < 8; nt++) {
                int c0 = kb + nt * 8 + 2 * tc;
                float z0 = sacc[nt][0] * CSC;
                float z1 = sacc[nt][1] * CSC;
                float z2 = sacc[nt][2] * CSC;
                float z3 = sacc[nt][3] * CSC;
                if (need_mask) {
                    if (c0     > gr0) z0 = -1e30f;
                    if (c0 + 1 > gr0) z1 = -1e30f;
                    if (c0     > gr0 + 8) z2 = -1e30f;
                    if (c0 + 1 > gr0 + 8) z3 = -1e30f;
                }
                sacc[nt][0] = z0; sacc[nt][1] = z1;
                sacc[nt][2] = z2; sacc[nt][3] = z3;
                mx0 = fmaxf(mx0, fmaxf(z0, z1));
                mx1 = fmaxf(mx1, fmaxf(z2, z3));
            }
            mx0 = fmaxf(mx0, __shfl_xor_sync(0xffffffffu, mx0, 1));
            mx0 = fmaxf(mx0, __shfl_xor_sync(0xffffffffu, mx0, 2));
            mx1 = fmaxf(mx1, __shfl_xor_sync(0xffffffffu, mx1, 1));
            mx1 = fmaxf(mx1, __shfl_xor_sync(0xffffffffu, mx1, 2));

            float m0n = fmaxf(m0, mx0);
            float m1n = fmaxf(m1, mx1);
            float f0 = exp2f(m0 - m0n);
            float f1 = exp2f(m1 - m1n);

            uint32_t pcu[8][4];
            float sum0 = 0.f, sum1 = 0.f;
#pragma unroll
            for (int nt = 0; nt < 8; nt++) {
                float p00 = exp2f(sacc[nt][0] - m0n);
                float p01 = exp2f(sacc[nt][1] - m0n);
                float p10 = exp2f(sacc[nt][2] - m1n);
                float p11 = exp2f(sacc[nt][3] - m1n);
                sum0 += p00 + p01;
                sum1 += p10 + p11;
                pcu[nt][0] = f2tf32(p00);
                pcu[nt][1] = f2tf32(p01);
                pcu[nt][2] = f2tf32(p10);
                pcu[nt][3] = f2tf32(p11);
            }
            sum0 += __shfl_xor_sync(0xffffffffu, sum0, 1);
            sum0 += __shfl_xor_sync(0xffffffffu, sum0, 2);
            sum1 += __shfl_xor_sync(0xffffffffu, sum1, 1);
            sum1 += __shfl_xor_sync(0xffffffffu, sum1, 2);

            l0 = l0 * f0 + sum0;
            l1 = l1 * f1 + sum1;
            m0 = m0n; m1 = m1n;
#pragma unroll
            for (int nt = 0; nt < 8; nt++) {
                oacc[nt][0] *= f0; oacc[nt][1] *= f0;
                oacc[nt][2] *= f1; oacc[nt][3] *= f1;
            }

            // ---- O += P @ V : C-fragment IS the k-permuted A-fragment ----
#pragma unroll
            for (int kt = 0; kt < 8; kt++) {
                uint32_t pa[4];
                pa[0] = pcu[kt][0];
                pa[1] = pcu[kt][2];
                pa[2] = pcu[kt][1];
                pa[3] = pcu[kt][3];
                const float* vrow = Vsm + (size_t)(kt * 8 + 2 * tc) * PK_V;
#pragma unroll
                for (int nt = 0; nt < 8; nt++) {
                    uint32_t vb[2];
                    vb[0] = __float_as_uint(vrow[nt * 8 + tr]);
                    vb[1] = __float_as_uint(vrow[PK_V + nt * 8 + tr]);
                    mma_tf32(oacc[nt], pa, vb);
                }
            }
        }

        st_cur = (st_cur == 2) ? 0 : st_cur + 1;
        st_nxt = (st_nxt == 2) ? 0 : st_nxt + 1;
    }

    // Epilogue: normalize, round to tf32, write to g_attn
    float il0 = 1.0f / l0;
    float il1 = 1.0f / l1;
    float* obase = g_attn + (size_t)(rowbase + gr0) * EMBED + h * HDIM + 2 * tc;
#pragma unroll
    for (int nt = 0; nt < 8; nt++) {
        *reinterpret_cast<float2*>(obase + nt * 8) =
            make_float2(roundtf(oacc[nt][0] * il0), roundtf(oacc[nt][1] * il0));
        *reinterpret_cast<float2*>(obase + 8 * EMBED + nt * 8) =
            make_float2(roundtf(oacc[nt][2] * il1), roundtf(oacc[nt][3] * il1));
    }
}

// ---------------------------------------------------------------------------
// Launch
// ---------------------------------------------------------------------------
extern "C" void kernel_launch(void* const* d_in, const int* in_sizes, int n_in,
                              void* d_out, int out_size)
{
    const float* x     = (const float*)d_in[0];
    const float* qkv_w = (const float*)d_in[1];
    const float* out_w = (const float*)d_in[2];
    float* out = (float*)d_out;

    static bool attr_done = false;
    if (!attr_done) {
        cudaFuncSetAttribute(gemm_tf32<true>,  cudaFuncAttributeMaxDynamicSharedMemorySize, GEMM_SMEM);
        cudaFuncSetAttribute(gemm_tf32<false>, cudaFuncAttributeMaxDynamicSharedMemorySize, GEMM_SMEM);
        cudaFuncSetAttribute(attn_tc_kernel,   cudaFuncAttributeMaxDynamicSharedMemorySize, ATT_SMEM);
        attr_done = true;
    }

    float *qkv, *attn, *xt, *w1t, *w2t;
    cudaGetSymbolAddress((void**)&qkv,  g_qkv);
    cudaGetSymbolAddress((void**)&attn, g_attn);
    cudaGetSymbolAddress((void**)&xt,   g_x_t);
    cudaGetSymbolAddress((void**)&w1t,  g_w1_t);
    cudaGetSymbolAddress((void**)&w2t,  g_w2_t);

    // 0) pre-round all inputs to tf32 in ONE launch
    round_all_kernel<<<(N4_ALL + 255) / 256, 256>>>(x, qkv_w, out_w, xt, w1t, w2t);

    // 1) QKV projection
    {
        dim3 grid(D3 / 128, MROWS / 128);
        gemm_tf32<true><<<grid, 128, GEMM_SMEM>>>(xt, w1t, qkv, MROWS, D3, EMBED);
    }

    // 2) Causal flash attention
    {
        dim3 grid(SEQ / TQA, NHEADS, BATCH);
        attn_tc_kernel<<<grid, 256, ATT_SMEM>>>();
    }

    // 3) Output projection
    {
        dim3 grid(EMBED / 128, MROWS / 128);
        gemm_tf32<false><<<grid, 128, GEMM_SMEM>>>(attn, w2t, out, MROWS, EMBED, EMBED);
    }
}

// round 17
// speedup vs baseline: 1.1566x; 1.0972x over previous
#include <cuda_runtime.h>
#include <cuda_bf16.h>
#include <cstdint>

// Problem constants
#define BATCH   2
#define SEQ     2048
#define EMBED   1024
#define NHEADS  16
#define HDIM    64
#define D3      (3 * EMBED)          // 3072
#define MROWS   (BATCH * SEQ)        // 4096

// ---------------------------------------------------------------------------
// Scratch (static device globals: allocation-free per harness rules)
// ---------------------------------------------------------------------------
__device__ float g_qkv [(size_t)MROWS * D3];      // (4096, 3072), tf32-rounded
__device__ float g_attn[(size_t)MROWS * EMBED];   // (4096, 1024), tf32-rounded

__device__ __align__(16) float g_x_t [(size_t)MROWS * EMBED];
__device__ __align__(16) float g_w1_t[(size_t)D3 * EMBED];
__device__ __align__(16) float g_w2_t[(size_t)EMBED * EMBED];

__device__ unsigned int g_wctr;                   // attention work-steal counter

// ---------------------------------------------------------------------------
// PTX helpers
// ---------------------------------------------------------------------------
__device__ __forceinline__ uint32_t smem_u32(const void* p) {
    uint32_t a;
    asm("{ .reg .u64 t; cvta.to.shared.u64 t, %1; cvt.u32.u64 %0, t; }" : "=r"(a) : "l"(p));
    return a;
}
__device__ __forceinline__ void cp_async16(uint32_t dst, const void* src) {
    asm volatile("cp.async.cg.shared.global [%0], [%1], 16;" :: "r"(dst), "l"(src));
}
__device__ __forceinline__ void cp_commit() {
    asm volatile("cp.async.commit_group;" ::: "memory");
}
template <int N>
__device__ __forceinline__ void cp_wait() {
    asm volatile("cp.async.wait_group %0;" :: "n"(N) : "memory");
}
__device__ __forceinline__ uint32_t f2tf32(float f) {
    uint32_t r;
    asm("cvt.rna.tf32.f32 %0, %1;" : "=r"(r) : "f"(f));
    return r;
}
__device__ __forceinline__ float roundtf(float f) {
    return __uint_as_float(f2tf32(f));
}
__device__ __forceinline__ void mma_tf32(float* c, const uint32_t* a, const uint32_t* b) {
    asm volatile(
        "mma.sync.aligned.m16n8k8.row.col.f32.tf32.tf32.f32 "
        "{%0,%1,%2,%3}, {%4,%5,%6,%7}, {%8,%9}, {%0,%1,%2,%3};"
        : "+f"(c[0]), "+f"(c[1]), "+f"(c[2]), "+f"(c[3])
        : "r"(a[0]), "r"(a[1]), "r"(a[2]), "r"(a[3]), "r"(b[0]), "r"(b[1]));
}

// ---------------------------------------------------------------------------
// Fused fp32 -> tf32-rounded copy over three concatenated tensors.
// Also resets the attention work-steal counter (runs first every replay).
// ---------------------------------------------------------------------------
#define N4_X   (MROWS * EMBED / 4)
#define N4_W1  (D3 * EMBED / 4)
#define N4_W2  (EMBED * EMBED / 4)
#define N4_ALL (N4_X + N4_W1 + N4_W2)

__global__ void round_all_kernel(const float* __restrict__ x,
                                 const float* __restrict__ w1,
                                 const float* __restrict__ w2,
                                 float* __restrict__ xt,
                                 float* __restrict__ w1t,
                                 float* __restrict__ w2t,
                                 unsigned int npers)
{
    int i = blockIdx.x * blockDim.x + threadIdx.x;
    if (i == 0) g_wctr = npers;    // reset work-steal counter each replay
    if (i >= N4_ALL) return;
    const float4* src;
    float4* dst;
    if (i < N4_X) {
        src = reinterpret_cast<const float4*>(x) + i;
        dst = reinterpret_cast<float4*>(xt) + i;
    } else if (i < N4_X + N4_W1) {
        src = reinterpret_cast<const float4*>(w1) + (i - N4_X);
        dst = reinterpret_cast<float4*>(w1t) + (i - N4_X);
    } else {
        src = reinterpret_cast<const float4*>(w2) + (i - N4_X - N4_W1);
        dst = reinterpret_cast<float4*>(w2t) + (i - N4_X - N4_W1);
    }
    float4 v = *src;
    float4 o;
    o.x = roundtf(v.x); o.y = roundtf(v.y); o.z = roundtf(v.z); o.w = roundtf(v.w);
    *dst = o;
}

// ---------------------------------------------------------------------------
// TF32 GEMM (R16 proven config, unchanged): C[M,N] = A[M,K] * B[N,K]^T.
// BM=BN=128, BK=32, 4 warps, warp tile 64x64, 2 CTAs/SM, 3-stage cp.async.
// ---------------------------------------------------------------------------
#define GROWF    36
#define GROWB    (GROWF * 4)
#define GTILE_B  (128 * GROWB)               // 18432
#define GSTAGE_B (2 * GTILE_B)               // 36864
#define GEMM_SMEM (3 * GSTAGE_B)             // 110592

__device__ __forceinline__ void load_stage_tf32(uint32_t sbase,
                                                const float* __restrict__ A,
                                                const float* __restrict__ B,
                                                int bm, int bn, int K, int k0, int tid)
{
#pragma unroll
    for (int rep = 0; rep < 16; rep++) {
        const int t = rep >> 3;
        int e   = tid + (rep & 7) * 128;
        int row = e >> 3;
        int ch  = e & 7;
        const float* src = (t == 0)
            ? A + (size_t)(bm + row) * K + k0 + ch * 4
            : B + (size_t)(bn + row) * K + k0 + ch * 4;
        cp_async16(sbase + (uint32_t)t * GTILE_B + (uint32_t)(row * GROWB + ch * 16), src);
    }
}

template <bool ROUND_C>
__global__ __launch_bounds__(128, 2) void gemm_tf32(
    const float* __restrict__ A, const float* __restrict__ B,
    float* __restrict__ C, int M, int N, int K)
{
    extern __shared__ __align__(16) float dynf[];
    const uint32_t sb = smem_u32(dynf);

    const int tid  = threadIdx.x;
    const int lane = tid & 31;
    const int wid  = tid >> 5;
    const int wm   = wid >> 1;
    const int wn   = wid & 1;
    const int tr   = lane >> 2;
    const int tc   = lane & 3;
    const int bm   = blockIdx.y * 128;
    const int bn   = blockIdx.x * 128;

    float acc[4][8][4];
#pragma unroll
    for (int i = 0; i < 4; i++)
#pragma unroll
        for (int j = 0; j < 8; j++)
#pragma unroll
            for (int k = 0; k < 4; k++) acc[i][j][k] = 0.f;

    const int NIT = K / 32;

    load_stage_tf32(sb + 0u * GSTAGE_B, A, B, bm, bn, K, 0, tid);
    cp_commit();
    load_stage_tf32(sb + 1u * GSTAGE_B, A, B, bm, bn, K, 32, tid);
    cp_commit();

    int st_cur = 0, st_nxt = 2;

    for (int it = 0; it < NIT; it++) {
        if (it + 1 < NIT) cp_wait<1>(); else cp_wait<0>();
        __syncthreads();

        if (it + 2 < NIT) {
            load_stage_tf32(sb + (uint32_t)st_nxt * GSTAGE_B,
                            A, B, bm, bn, K, (it + 2) * 32, tid);
            cp_commit();
        }

        const float* As = dynf + (size_t)st_cur * (GSTAGE_B / 4);
        const float* Bs = As + GTILE_B / 4;

#pragma unroll
        for (int kt = 0; kt < 4; kt++) {
            const int k0 = kt * 8;

            uint32_t afr[4][4];
#pragma unroll
            for (int mt = 0; mt < 4; mt++) {
                const float* ap = As + (size_t)(wm * 64 + mt * 16 + tr) * GROWF + k0 + tc;
                afr[mt][0] = __float_as_uint(ap[0]);
                afr[mt][1] = __float_as_uint(ap[8 * GROWF]);
                afr[mt][2] = __float_as_uint(ap[4]);
                afr[mt][3] = __float_as_uint(ap[8 * GROWF + 4]);
            }

#pragma unroll
            for (int nt = 0; nt < 8; nt++) {
                const float* bp = Bs + (size_t)(wn * 64 + nt * 8 + tr) * GROWF + k0 + tc;
                uint32_t bb[2];
                bb[0] = __float_as_uint(bp[0]);
                bb[1] = __float_as_uint(bp[4]);
#pragma unroll
                for (int mt = 0; mt < 4; mt++)
                    mma_tf32(acc[mt][nt], afr[mt], bb);
            }
        }

        st_cur = (st_cur == 2) ? 0 : st_cur + 1;
        st_nxt = (st_nxt == 2) ? 0 : st_nxt + 1;
    }

#pragma unroll
    for (int mt = 0; mt < 4; mt++) {
        int row = bm + wm * 64 + mt * 16 + tr;
#pragma unroll
        for (int nt = 0; nt < 8; nt++) {
            int col = bn + wn * 64 + nt * 8 + tc * 2;
            float c0 = acc[mt][nt][0], c1 = acc[mt][nt][1];
            float c2 = acc[mt][nt][2], c3 = acc[mt][nt][3];
            if (ROUND_C) {
                c0 = roundtf(c0); c1 = roundtf(c1);
                c2 = roundtf(c2); c3 = roundtf(c3);
            }
            *reinterpret_cast<float2*>(&C[(size_t)row * N + col]) = make_float2(c0, c1);
            *reinterpret_cast<float2*>(&C[(size_t)(row + 8) * N + col]) = make_float2(c2, c3);
        }
    }
}

// ---------------------------------------------------------------------------
// TF32 causal flash attention, PERSISTENT CTAs + atomic work stealing.
// Inner loops identical to the R14/R16 proven config.
// Work item t in [0, 512): qi = 15 - (t>>5) (largest first), h = (t&31)>>1,
// b = t&1. Counter g_wctr initialized to gridDim by round_all_kernel.
// ---------------------------------------------------------------------------
#define TQA   128
#define TKA   64
#define PK_K  72
#define PK_V  68
#define KT_F  (64 * PK_K)
#define VT_F  (64 * PK_V)
#define STG_F (KT_F + VT_F)
#define ATT_SMEM (3 * STG_F * 4)            // 107520 bytes
#define NITEMS  (16 * NHEADS * BATCH)       // 512

__device__ __forceinline__ void attn_load_kv(uint32_t sst,
                                             const float* __restrict__ kptr,
                                             const float* __restrict__ vptr,
                                             int kb, int tid)
{
#pragma unroll
    for (int rep = 0; rep < 4; rep++) {
        int i = tid + rep * 256;
        int r = i >> 4, c4 = (i & 15) * 4;
        cp_async16(sst + (uint32_t)(r * PK_K + c4) * 4,
                   kptr + (size_t)(kb + r) * D3 + c4);
        cp_async16(sst + KT_F * 4 + (uint32_t)(r * PK_V + c4) * 4,
                   vptr + (size_t)(kb + r) * D3 + c4);
    }
    cp_commit();
}

__global__ __launch_bounds__(256, 1) void attn_tc_kernel()
{
    extern __shared__ float smf[];
    __shared__ int s_next;

    const int tid  = threadIdx.x;
    const int lane = tid & 31;
    const int w    = tid >> 5;
    const int tr   = lane >> 2;
    const int tc   = lane & 3;
    const uint32_t s0 = smem_u32(smf);

    int item = blockIdx.x;

    while (item < NITEMS) {
        const int qi = 15 - (item >> 5);
        const int hb = item & 31;
        const int h  = hb >> 1;
        const int b  = hb & 1;
        const int qb = qi * TQA;
        const size_t rowbase = (size_t)b * SEQ;

        const float* qptr = g_qkv + rowbase * D3 + h * HDIM;
        const float* kptr = qptr + EMBED;
        const float* vptr = qptr + 2 * EMBED;

        // Stage Q tile through smem (stride PK_K), then to registers.
        for (int i = tid; i < 128 * 16; i += 256) {
            int r = i >> 4, c4 = (i & 15) * 4;
            float4 v = *reinterpret_cast<const float4*>(qptr + (size_t)(qb + r) * D3 + c4);
            float* dst = smf + r * PK_K + c4;
            dst[0] = v.x; dst[1] = v.y; dst[2] = v.z; dst[3] = v.w;
        }
        __syncthreads();

        uint32_t qfrag[8][4];
        {
            const float* qrow = smf + (size_t)(w * 16 + tr) * PK_K + 2 * tc;
#pragma unroll
            for (int kt = 0; kt < 8; kt++) {
                float2 lo = *reinterpret_cast<const float2*>(qrow + kt * 8);
                float2 hi = *reinterpret_cast<const float2*>(qrow + 8 * PK_K + kt * 8);
                qfrag[kt][0] = __float_as_uint(lo.x);
                qfrag[kt][2] = __float_as_uint(lo.y);
                qfrag[kt][1] = __float_as_uint(hi.x);
                qfrag[kt][3] = __float_as_uint(hi.y);
            }
        }
        __syncthreads();   // Q staging reads done; smem free for K/V stages

        float oacc[8][4];
#pragma unroll
        for (int nt = 0; nt < 8; nt++)
#pragma unroll
            for (int e = 0; e < 4; e++) oacc[nt][e] = 0.f;

        float m0 = -1e30f, m1 = -1e30f, l0 = 0.f, l1 = 0.f;

        const float CSC = 0.18033688f;
        const int wrow  = qb + w * 16;
        const int gr0   = wrow + tr;
        const int jmax  = (qb + TQA - 1) / TKA;

        attn_load_kv(s0 + 0u * STG_F * 4, kptr, vptr, 0, tid);
        attn_load_kv(s0 + 1u * STG_F * 4, kptr, vptr, TKA, tid);

        int st_cur = 0, st_nxt = 2;

        for (int j = 0; j <= jmax; j++) {
            const int kb = j * TKA;

            if (j < jmax) cp_wait<1>(); else cp_wait<0>();
            __syncthreads();

            if (j + 2 <= jmax)
                attn_load_kv(s0 + (uint32_t)st_nxt * STG_F * 4, kptr, vptr, (j + 2) * TKA, tid);

            const float* Ksm = smf + st_cur * STG_F;
            const float* Vsm = Ksm + KT_F;

            if (kb <= wrow + 15) {
                float sacc[8][4];
#pragma unroll
                for (int nt = 0; nt < 8; nt++)
#pragma unroll
                    for (int e = 0; e < 4; e++) sacc[nt][e] = 0.f;

                const float* kbase = Ksm + (size_t)tr * PK_K + 2 * tc;
#pragma unroll
                for (int kt = 0; kt < 8; kt++) {
#pragma unroll
                    for (int nt = 0; nt < 8; nt++) {
                        float2 kv2 = *reinterpret_cast<const float2*>(
                            kbase + (size_t)nt * 8 * PK_K + kt * 8);
                        uint32_t bb[2];
                        bb[0] = __float_as_uint(kv2.x);
                        bb[1] = __float_as_uint(kv2.y);
                        mma_tf32(sacc[nt], qfrag[kt], bb);
                    }
                }

                const bool need_mask = (kb + TKA - 1) > wrow;
                float mx0 = -1e30f, mx1 = -1e30f;
#pragma unroll
                for (int nt = 0; nt < 8; nt++) {
                    int c0 = kb + nt * 8 + 2 * tc;
                    float z0 = sacc[nt][0] * CSC;
                    float z1 = sacc[nt][1] * CSC;
                    float z2 = sacc[nt][2] * CSC;
                    float z3 = sacc[nt][3] * CSC;
                    if (need_mask) {
                        if (c0     > gr0) z0 = -1e30f;
                        if (c0 + 1 > gr0) z1 = -1e30f;
                        if (c0     > gr0 + 8) z2 = -1e30f;
                        if (c0 + 1 > gr0 + 8) z3 = -1e30f;
                    }
                    sacc[nt][0] = z0; sacc[nt][1] = z1;
                    sacc[nt][2] = z2; sacc[nt][3] = z3;
                    mx0 = fmaxf(mx0, fmaxf(z0, z1));
                    mx1 = fmaxf(mx1, fmaxf(z2, z3));
                }
                mx0 = fmaxf(mx0, __shfl_xor_sync(0xffffffffu, mx0, 1));
                mx0 = fmaxf(mx0, __shfl_xor_sync(0xffffffffu, mx0, 2));
                mx1 = fmaxf(mx1, __shfl_xor_sync(0xffffffffu, mx1, 1));
                mx1 = fmaxf(mx1, __shfl_xor_sync(0xffffffffu, mx1, 2));

                float m0n = fmaxf(m0, mx0);
                float m1n = fmaxf(m1, mx1);
                float f0 = exp2f(m0 - m0n);
                float f1 = exp2f(m1 - m1n);

                uint32_t pcu[8][4];
                float sum0 = 0.f, sum1 = 0.f;
#pragma unroll
                for (int nt = 0; nt < 8; nt++) {
                    float p00 = exp2f(sacc[nt][0] - m0n);
                    float p01 = exp2f(sacc[nt][1] - m0n);
                    float p10 = exp2f(sacc[nt][2] - m1n);
                    float p11 = exp2f(sacc[nt][3] - m1n);
                    sum0 += p00 + p01;
                    sum1 += p10 + p11;
                    pcu[nt][0] = f2tf32(p00);
                    pcu[nt][1] = f2tf32(p01);
                    pcu[nt][2] = f2tf32(p10);
                    pcu[nt][3] = f2tf32(p11);
                }
                sum0 += __shfl_xor_sync(0xffffffffu, sum0, 1);
                sum0 += __shfl_xor_sync(0xffffffffu, sum0, 2);
                sum1 += __shfl_xor_sync(0xffffffffu, sum1, 1);
                sum1 += __shfl_xor_sync(0xffffffffu, sum1, 2);

                l0 = l0 * f0 + sum0;
                l1 = l1 * f1 + sum1;
                m0 = m0n; m1 = m1n;
#pragma unroll
                for (int nt = 0; nt < 8; nt++) {
                    oacc[nt][0] *= f0; oacc[nt][1] *= f0;
                    oacc[nt][2] *= f1; oacc[nt][3] *= f1;
                }

                // O += P @ V : C-fragment IS the k-permuted A-fragment
#pragma unroll
                for (int kt = 0; kt < 8; kt++) {
                    uint32_t pa[4];
                    pa[0] = pcu[kt][0];
                    pa[1] = pcu[kt][2];
                    pa[2] = pcu[kt][1];
                    pa[3] = pcu[kt][3];
                    const float* vrow = Vsm + (size_t)(kt * 8 + 2 * tc) * PK_V;
#pragma unroll
                    for (int nt = 0; nt < 8; nt++) {
                        uint32_t vb[2];
                        vb[0] = __float_as_uint(vrow[nt * 8 + tr]);
                        vb[1] = __float_as_uint(vrow[PK_V + nt * 8 + tr]);
                        mma_tf32(oacc[nt], pa, vb);
                    }
                }
            }

            st_cur = (st_cur == 2) ? 0 : st_cur + 1;
            st_nxt = (st_nxt == 2) ? 0 : st_nxt + 1;
        }

        // Epilogue: normalize, round to tf32, write to g_attn
        float il0 = 1.0f / l0;
        float il1 = 1.0f / l1;
        float* obase = g_attn + (size_t)(rowbase + qb + w * 16 + tr) * EMBED + h * HDIM + 2 * tc;
#pragma unroll
        for (int nt = 0; nt < 8; nt++) {
            *reinterpret_cast<float2*>(obase + nt * 8) =
                make_float2(roundtf(oacc[nt][0] * il0), roundtf(oacc[nt][1] * il0));
            *reinterpret_cast<float2*>(obase + 8 * EMBED + nt * 8) =
                make_float2(roundtf(oacc[nt][2] * il1), roundtf(oacc[nt][3] * il1));
        }

        // Steal next item
        if (tid == 0) s_next = (int)atomicAdd(&g_wctr, 1u);
        __syncthreads();   // s_next visible; also guards smem reuse next item
        item = s_next;
    }
}

// ---------------------------------------------------------------------------
// Launch
// ---------------------------------------------------------------------------
extern "C" void kernel_launch(void* const* d_in, const int* in_sizes, int n_in,
                              void* d_out, int out_size)
{
    const float* x     = (const float*)d_in[0];
    const float* qkv_w = (const float*)d_in[1];
    const float* out_w = (const float*)d_in[2];
    float* out = (float*)d_out;

    static bool attr_done = false;
    static int npers = 148;
    if (!attr_done) {
        cudaFuncSetAttribute(gemm_tf32<true>,  cudaFuncAttributeMaxDynamicSharedMemorySize, GEMM_SMEM);
        cudaFuncSetAttribute(gemm_tf32<false>, cudaFuncAttributeMaxDynamicSharedMemorySize, GEMM_SMEM);
        cudaFuncSetAttribute(attn_tc_kernel,   cudaFuncAttributeMaxDynamicSharedMemorySize, ATT_SMEM);
        int dev = 0;
        cudaGetDevice(&dev);
        int smc = 0;
        if (cudaDeviceGetAttribute(&smc, cudaDevAttrMultiProcessorCount, dev) == cudaSuccess && smc > 0)
            npers = smc;
        if (npers > NITEMS) npers = NITEMS;
        attr_done = true;
    }

    float *qkv, *attn, *xt, *w1t, *w2t;
    cudaGetSymbolAddress((void**)&qkv,  g_qkv);
    cudaGetSymbolAddress((void**)&attn, g_attn);
    cudaGetSymbolAddress((void**)&xt,   g_x_t);
    cudaGetSymbolAddress((void**)&w1t,  g_w1_t);
    cudaGetSymbolAddress((void**)&w2t,  g_w2_t);

    // 0) pre-round all inputs to tf32 + reset work-steal counter
    round_all_kernel<<<(N4_ALL + 255) / 256, 256>>>(x, qkv_w, out_w, xt, w1t, w2t,
                                                    (unsigned int)npers);

    // 1) QKV projection
    {
        dim3 grid(D3 / 128, MROWS / 128);
        gemm_tf32<true><<<grid, 128, GEMM_SMEM>>>(xt, w1t, qkv, MROWS, D3, EMBED);
    }

    // 2) Causal flash attention (persistent CTAs, work stealing)
    attn_tc_kernel<<<npers, 256, ATT_SMEM>>>();

    // 3) Output projection
    {
        dim3 grid(EMBED / 128, MROWS / 128);
        gemm_tf32<false><<<grid, 128, GEMM_SMEM>>>(attn, w2t, out, MROWS, EMBED, EMBED);
    }
}